// round 5
// baseline (speedup 1.0000x reference)
#include <cuda_runtime.h>
#include <cstdint>
#include <math_constants.h>

#define BATCH 4096
#define VSZ   256
#define NU    129
#define SKIP  25
#define NEGINF (-CUDART_INF_F)
#define FULL  0xFFFFFFFFu

#define ROW_BYTES   516
#define GROUP_ROWS  4
#define GROUP_BYTES 2064                     // 516*4, 16B multiple
#define FIRST_ROW   24                       // 516*24 is 16B aligned
#define NGROUPS     58
#define NSLOTS      3
#define WPB         8                        // warps per block (256 threads)

// Strictly monotone float -> uint32 key (order-preserving bijection) + inverse
static __device__ __forceinline__ unsigned fkey(float f) {
    unsigned u = __float_as_uint(f);
    return u ^ ((unsigned)((int)u >> 31) | 0x80000000u);
}
static __device__ __forceinline__ float fkey_inv(unsigned k) {
    unsigned m = (k & 0x80000000u) ? 0x80000000u : 0xFFFFFFFFu;
    return __uint_as_float(k ^ m);
}

static __device__ __forceinline__ uint32_t smem_u32(const void* p) {
    uint32_t a;
    asm("{ .reg .u64 t; cvta.to.shared.u64 t, %1; cvt.u32.u64 %0, t; }" : "=r"(a) : "l"(p));
    return a;
}
static __device__ __forceinline__ void mbar_init(uint32_t mbar, uint32_t cnt) {
    asm volatile("mbarrier.init.shared.b64 [%0], %1;" :: "r"(mbar), "r"(cnt) : "memory");
}
static __device__ __forceinline__ void mbar_expect_tx(uint32_t mbar, uint32_t bytes) {
    asm volatile("mbarrier.arrive.expect_tx.shared.b64 _, [%0], %1;"
                 :: "r"(mbar), "r"(bytes) : "memory");
}
static __device__ __forceinline__ void bulk_g2s(uint32_t dst, const void* src, uint32_t bytes, uint32_t mbar) {
    asm volatile("cp.async.bulk.shared::cta.global.mbarrier::complete_tx::bytes [%0], [%1], %2, [%3];"
                 :: "r"(dst), "l"(src), "r"(bytes), "r"(mbar) : "memory");
}
static __device__ __forceinline__ void mbar_wait(uint32_t mbar, uint32_t parity) {
    uint32_t done;
    asm volatile("{\n\t.reg .pred p;\n\t"
                 "mbarrier.try_wait.parity.acquire.cta.shared::cta.b64 p, [%1], %2;\n\t"
                 "selp.b32 %0, 1, 0, p;\n\t}"
                 : "=r"(done) : "r"(mbar), "r"(parity) : "memory");
    if (!done) {
        asm volatile("{\n\t.reg .pred P1;\n\t"
                     "W_%=:\n\t"
                     "mbarrier.try_wait.parity.acquire.cta.shared::cta.b64 P1, [%0], %1, 0x989680;\n\t"
                     "@P1 bra.uni D_%=;\n\t"
                     "bra.uni W_%=;\n\t"
                     "D_%=:\n\t}"
                     :: "r"(mbar), "r"(parity) : "memory");
    }
}

__global__ void __launch_bounds__(256, 4)
greedy_matching_kernel(const float* __restrict__ x, float* __restrict__ out) {
    __shared__ __align__(128) unsigned char sbuf[WPB][NSLOTS][GROUP_BYTES];
    __shared__ __align__(8)   unsigned long long smbar[WPB][NSLOTS];

    const int wib  = threadIdx.x >> 5;
    const int lane = threadIdx.x & 31;
    const int warp = blockIdx.x * WPB + wib;

    const float* __restrict__ base = x + (size_t)warp * (VSZ * NU);
    float* __restrict__ pi_out = out + BATCH + (size_t)warp * VSZ;

    const uint32_t sb  = smem_u32(&sbuf[wib][0][0]);
    const uint32_t mbb = smem_u32(&smbar[wib][0]);

    if (lane == 0) {
        mbar_init(mbb + 0, 1); mbar_init(mbb + 8, 1); mbar_init(mbb + 16, 1);
        asm volatile("fence.proxy.async.shared::cta;" ::: "memory");
#pragma unroll
        for (int s = 0; s < NSLOTS; ++s) {
            mbar_expect_tx(mbb + 8u * s, GROUP_BYTES);
            bulk_g2s(sb + s * GROUP_BYTES,
                     base + (size_t)(FIRST_ROW + GROUP_ROWS * s) * NU,
                     GROUP_BYTES, mbb + 8u * s);
        }
    }
    __syncwarp();

    // Skip phase t = 0..23 (t = 24 goes out with group 0's vector store)
    if (lane < FIRST_ROW) pi_out[lane] = 0.0f;

    // Availability bias: 0 = available, -inf = matched.
    // Lane l owns j = l, l+32, l+64, l+96; j = 128 real only on lane 0.
    float b0 = 0.f, b1 = 0.f, b2 = 0.f, b3 = 0.f;
    float b4 = (lane == 0) ? 0.f : NEGINF;
    const float z0 = (lane == 0) ? 0.f : 1.f;  // forces skip weight to 0 on lane 0
    float size = 0.f;

#define LOADW(P, rp) \
    float P##0 = (rp)[lane];      float P##1 = (rp)[lane + 32]; \
    float P##2 = (rp)[lane + 64]; float P##3 = (rp)[lane + 96]; \
    float P##4 = (rp)[128];

    // Speculative per-row lane-local max/arg with group-entry bias.
    // Strict '>' keeps the smallest owned j on in-lane ties.
#define SPEC(P, MK, LI) do {                                                   \
        float f0 = fmaf(P##0, z0, b0);                                         \
        float f1 = P##1 + b1;                                                  \
        float f2 = P##2 + b2;                                                  \
        float f3 = P##3 + b3;                                                  \
        float f4 = P##4 + b4;                                                  \
        float m01 = fmaxf(f0, f1), m23 = fmaxf(f2, f3);                        \
        float m03 = fmaxf(m01, m23);                                           \
        float lm  = fmaxf(m03, f4);                                            \
        int j01 = (f1 > f0)  ? lane + 32 : lane;                               \
        int j23 = (f3 > f2)  ? lane + 96 : lane + 64;                          \
        int jlo = (m23 > m01) ? j23 : j01;                                     \
        LI = (f4 > m03) ? 128 : jlo;                                           \
        MK = fkey(lm);                                                         \
    } while (0)

    // Exact recompute of one row excluding prior in-group selections ea/eb/ec
    // (-1 = none). Rare path.
#define RECOMP(P, EA, EB, EC, SOUT, GFOUT) do {                                \
        int ja = lane, jb = lane + 32, jc = lane + 64, jd = lane + 96;         \
        float f0 = ((ja==(EA))|(ja==(EB))|(ja==(EC))) ? NEGINF : fmaf(P##0, z0, b0); \
        float f1 = ((jb==(EA))|(jb==(EB))|(jb==(EC))) ? NEGINF : P##1 + b1;    \
        float f2 = ((jc==(EA))|(jc==(EB))|(jc==(EC))) ? NEGINF : P##2 + b2;    \
        float f3 = ((jd==(EA))|(jd==(EB))|(jd==(EC))) ? NEGINF : P##3 + b3;    \
        float f4 = ((128==(EA))|(128==(EB))|(128==(EC))) ? NEGINF : P##4 + b4; \
        float m01 = fmaxf(f0, f1), m23 = fmaxf(f2, f3);                        \
        float m03 = fmaxf(m01, m23);                                           \
        float lm  = fmaxf(m03, f4);                                            \
        int j01 = (f1 > f0)  ? lane + 32 : lane;                               \
        int j23 = (f3 > f2)  ? lane + 96 : lane + 64;                          \
        int jlo = (m23 > m01) ? j23 : j01;                                     \
        int li  = (f4 > m03) ? 128 : jlo;                                      \
        unsigned mk = fkey(lm);                                                \
        unsigned gk = __reduce_max_sync(FULL, mk);                             \
        unsigned cd = (mk == gk) ? (unsigned)li : FULL;                        \
        SOUT = (int)__reduce_min_sync(FULL, cd);                               \
        GFOUT = fkey_inv(gk);                                                  \
    } while (0)

#define MASKUPD(S) do {                                                        \
        int d = (S) - lane;                                                    \
        if (d == 0 && (S) != 0) b0 = NEGINF;                                   \
        if (d == 32)  b1 = NEGINF;                                             \
        if (d == 64)  b2 = NEGINF;                                             \
        if (d == 96)  b3 = NEGINF;                                             \
        if (d == 128) b4 = NEGINF;                                             \
    } while (0)

    int stage = 0, phase = 0;

    // ── Group 0: rows 24..27; row 24 is skip. 3 speculative live steps.
    {
        mbar_wait(mbb + 0, 0);
        const char* sp = (const char*)&sbuf[wib][0][0];
        LOADW(B, (const float*)(sp + 1 * ROW_BYTES));
        LOADW(C, (const float*)(sp + 2 * ROW_BYTES));
        LOADW(D, (const float*)(sp + 3 * ROW_BYTES));
        unsigned mkB, mkC, mkD; int liB, liC, liD;
        SPEC(B, mkB, liB); SPEC(C, mkC, liC); SPEC(D, mkD, liD);
        unsigned gkB = __reduce_max_sync(FULL, mkB);
        unsigned gkC = __reduce_max_sync(FULL, mkC);
        unsigned gkD = __reduce_max_sync(FULL, mkD);
        unsigned cB = (mkB == gkB) ? (unsigned)liB : FULL;
        unsigned cC = (mkC == gkC) ? (unsigned)liC : FULL;
        unsigned cD = (mkD == gkD) ? (unsigned)liD : FULL;
        int s1 = (int)__reduce_min_sync(FULL, cB);
        int s2 = (int)__reduce_min_sync(FULL, cC);
        int s3 = (int)__reduce_min_sync(FULL, cD);

        float gf1 = fkey_inv(gkB);
        size += gf1;
        int e0 = s1 ? s1 : -1;
        float gf2 = fkey_inv(gkC);
        if (s2 == e0) RECOMP(C, e0, -1, -1, s2, gf2);
        size += gf2;
        int e1 = s2 ? s2 : -1;
        float gf3 = fkey_inv(gkD);
        if (s3 == e0 || s3 == e1) RECOMP(D, e0, e1, -1, s3, gf3);
        size += gf3;

        MASKUPD(s1); MASKUPD(s2); MASKUPD(s3);

        if (lane == 0) {
            *(float4*)(pi_out + FIRST_ROW) =
                make_float4(0.0f, __int2float_rn(s1), __int2float_rn(s2), __int2float_rn(s3));
            mbar_expect_tx(mbb + 0, GROUP_BYTES);
            bulk_g2s(sb + 0,
                     base + (size_t)(FIRST_ROW + GROUP_ROWS * NSLOTS) * NU,
                     GROUP_BYTES, mbb + 0);
        }
        stage = 1;
    }

    // ── Groups 1..57: 4 speculative steps each.
#pragma unroll 1
    for (int g = 1; g < NGROUPS; ++g) {
        mbar_wait(mbb + 8u * stage, phase);
        const char* sp = (const char*)&sbuf[wib][stage][0];
        LOADW(A, (const float*)(sp + 0 * ROW_BYTES));
        LOADW(B, (const float*)(sp + 1 * ROW_BYTES));
        LOADW(C, (const float*)(sp + 2 * ROW_BYTES));
        LOADW(D, (const float*)(sp + 3 * ROW_BYTES));

        unsigned mkA, mkB, mkC, mkD; int liA, liB, liC, liD;
        SPEC(A, mkA, liA); SPEC(B, mkB, liB); SPEC(C, mkC, liC); SPEC(D, mkD, liD);

        unsigned gkA = __reduce_max_sync(FULL, mkA);
        unsigned gkB = __reduce_max_sync(FULL, mkB);
        unsigned gkC = __reduce_max_sync(FULL, mkC);
        unsigned gkD = __reduce_max_sync(FULL, mkD);
        unsigned cA = (mkA == gkA) ? (unsigned)liA : FULL;
        unsigned cB = (mkB == gkB) ? (unsigned)liB : FULL;
        unsigned cC = (mkC == gkC) ? (unsigned)liC : FULL;
        unsigned cD = (mkD == gkD) ? (unsigned)liD : FULL;
        int s0 = (int)__reduce_min_sync(FULL, cA);
        int s1 = (int)__reduce_min_sync(FULL, cB);
        int s2 = (int)__reduce_min_sync(FULL, cC);
        int s3 = (int)__reduce_min_sync(FULL, cD);

        // Serial validation: spec for step k is exact unless its winner is a
        // prior nonzero in-group selection (masking a non-max never changes
        // an argmax; surviving min-index winner of a superset tie-set stays
        // the winner).
        size += fkey_inv(gkA);
        int e0 = s0 ? s0 : -1;

        float gf1 = fkey_inv(gkB);
        if (s1 == e0) RECOMP(B, e0, -1, -1, s1, gf1);
        size += gf1;
        int e1 = s1 ? s1 : -1;

        float gf2 = fkey_inv(gkC);
        if (s2 == e0 || s2 == e1) RECOMP(C, e0, e1, -1, s2, gf2);
        size += gf2;
        int e2 = s2 ? s2 : -1;

        float gf3 = fkey_inv(gkD);
        if (s3 == e0 || s3 == e1 || s3 == e2) RECOMP(D, e0, e1, e2, s3, gf3);
        size += gf3;

        MASKUPD(s0); MASKUPD(s1); MASKUPD(s2); MASKUPD(s3);

        const int t0 = FIRST_ROW + GROUP_ROWS * g;
        if (lane == 0) {
            *(float4*)(pi_out + t0) =
                make_float4(__int2float_rn(s0), __int2float_rn(s1),
                            __int2float_rn(s2), __int2float_rn(s3));
            if (g + NSLOTS < NGROUPS) {
                mbar_expect_tx(mbb + 8u * stage, GROUP_BYTES);
                bulk_g2s(sb + stage * GROUP_BYTES,
                         base + (size_t)(t0 + GROUP_ROWS * NSLOTS) * NU,
                         GROUP_BYTES, mbb + 8u * stage);
            }
        }
        if (++stage == NSLOTS) { stage = 0; phase ^= 1; }
    }

    if (lane == 0) out[warp] = -size;
}

extern "C" void kernel_launch(void* const* d_in, const int* in_sizes, int n_in,
                              void* d_out, int out_size) {
    const float* x = (const float*)d_in[0];
    float* out = (float*)d_out;
    greedy_matching_kernel<<<BATCH / WPB, 256>>>(x, out);
}

// round 6
// speedup vs baseline: 1.3282x; 1.3282x over previous
#include <cuda_runtime.h>
#include <cstdint>
#include <math_constants.h>

#define BATCH 4096
#define VSZ   256
#define NU    129
#define SKIP  25
#define NEGINF (-CUDART_INF_F)
#define FULL  0xFFFFFFFFu

// Strictly monotone float -> uint32 key (order-preserving bijection) + inverse
static __device__ __forceinline__ unsigned fkey(float f) {
    unsigned u = __float_as_uint(f);
    return u ^ ((unsigned)((int)u >> 31) | 0x80000000u);
}
static __device__ __forceinline__ float fkey_inv(unsigned k) {
    unsigned m = (k & 0x80000000u) ? 0x80000000u : 0xFFFFFFFFu;
    return __uint_as_float(k ^ m);
}
static __device__ __forceinline__ unsigned lanemask_lt() {
    unsigned m;
    asm("mov.u32 %0, %%lanemask_lt;" : "=r"(m));
    return m;
}

__global__ void __launch_bounds__(256, 4)
greedy_matching_kernel(const float* __restrict__ x, float* __restrict__ out) {
    const int warp = (blockIdx.x * blockDim.x + threadIdx.x) >> 5;
    const int lane = threadIdx.x & 31;

    const float* __restrict__ base = x + (size_t)warp * (VSZ * NU);
    float* __restrict__ pi_out = out + BATCH + (size_t)warp * VSZ;

    // Skip phase: sel = 0, weight 0, no mask change.
    for (int t = lane; t < SKIP; t += 32) pi_out[t] = 0.0f;

    // CONTIGUOUS ownership: lane l owns j = 4l, 4l+1, 4l+2, 4l+3.
    // j = 128 lives on lane 31 (largest index -> evaluated last, loses ties).
    // => j-ranges strictly increase with lane, so among key-tied lanes the
    //    lowest lane holds the smallest j: ballot + lowest-set-bit is an
    //    EXACT first-index tie-break. No second reduction, ever.
    float b0 = 0.f, b1 = 0.f, b2 = 0.f, b3 = 0.f;
    float b4 = (lane == 31) ? 0.f : NEGINF;
    const float z0 = (lane == 0) ? 0.f : 1.f;   // skip (j=0) weight forced to 0
    const unsigned lmlt = lanemask_lt();
    const int j0 = 4 * lane;
    float size = 0.f;

    // Ring of 3 prefetched rows. 231 live steps = 3 * 77.
    float a0,a1,a2,a3,a4, c0,c1,c2,c3,c4, e0,e1,e2,e3,e4;
    {
        const float* p = base + SKIP * NU + j0;
        a0 = p[0]; a1 = p[1]; a2 = p[2]; a3 = p[3];
        a4 = (lane == 31) ? p[128 - 124] : 0.f;          // base+SKIP*NU+128
        p += NU;
        c0 = p[0]; c1 = p[1]; c2 = p[2]; c3 = p[3];
        c4 = (lane == 31) ? p[128 - 124] : 0.f;
        p += NU;
        e0 = p[0]; e1 = p[1]; e2 = p[2]; e3 = p[3];
        e4 = (lane == 31) ? p[128 - 124] : 0.f;
    }

#define STAGE(B0,B1,B2,B3,B4, T)                                               \
    do {                                                                       \
        float f0 = fmaf(B0, z0, b0);                                           \
        float f1 = B1 + b1;                                                    \
        float f2 = B2 + b2;                                                    \
        float f3 = B3 + b3;                                                    \
        float f4 = B4 + b4;                                                    \
        /* refill this buffer with row min(T+3, VSZ-1); loads are off-chain */ \
        {                                                                      \
            int r = (T) + 3; r = (r < VSZ - 1) ? r : (VSZ - 1);                \
            const float* __restrict__ q = base + (size_t)r * NU + j0;          \
            B0 = q[0]; B1 = q[1]; B2 = q[2]; B3 = q[3];                        \
            B4 = (lane == 31) ? q[4] : 0.f;   /* j0=124 -> q[4] is col 128 */  \
        }                                                                      \
        float m01 = fmaxf(f0, f1), m23 = fmaxf(f2, f3);                        \
        float m03 = fmaxf(m01, m23);                                           \
        float lm  = fmaxf(m03, f4);                                            \
        /* in-lane argmax, strict '>' keeps the smallest j on ties */          \
        int jA = (f1 > f0)  ? j0 + 1 : j0;                                     \
        int jB = (f3 > f2)  ? j0 + 3 : j0 + 2;                                 \
        int jlo = (m23 > m01) ? jB : jA;                                       \
        int li  = (f4 > m03) ? 128 : jlo;                                      \
        unsigned mk = fkey(lm);                                                \
        unsigned gk = __reduce_max_sync(FULL, mk);                             \
        bool ismax = (mk == gk);                                               \
        unsigned eq = __ballot_sync(FULL, ismax);                              \
        bool win = ismax && ((eq & lmlt) == 0u);  /* lowest set bit = min j */ \
        size += fkey_inv(gk);                                                  \
        if (win && li != 0) {                                                  \
            if (li == 128)      b4 = NEGINF;                                   \
            else { int cc = li & 3;                                            \
                   if (cc == 0) b0 = NEGINF;                                   \
                   else if (cc == 1) b1 = NEGINF;                              \
                   else if (cc == 2) b2 = NEGINF;                              \
                   else b3 = NEGINF; }                                         \
        }                                                                      \
        int wl = __ffs(eq) - 1;                     /* uniform */              \
        int s  = __shfl_sync(FULL, li, wl);         /* off-chain */            \
        if (lane == 0) pi_out[T] = __int2float_rn(s);                          \
    } while (0)

#pragma unroll 1
    for (int t = SKIP; t < VSZ; t += 3) {
        STAGE(a0, a1, a2, a3, a4, t);
        STAGE(c0, c1, c2, c3, c4, t + 1);
        STAGE(e0, e1, e2, e3, e4, t + 2);
    }

    if (lane == 0) out[warp] = -size;
}

extern "C" void kernel_launch(void* const* d_in, const int* in_sizes, int n_in,
                              void* d_out, int out_size) {
    const float* x = (const float*)d_in[0];
    float* out = (float*)d_out;
    greedy_matching_kernel<<<BATCH / 8, 256>>>(x, out);
}

// round 7
// speedup vs baseline: 1.4148x; 1.0652x over previous
#include <cuda_runtime.h>
#include <cstdint>
#include <math_constants.h>

#define BATCH 4096
#define VSZ   256
#define NU    129
#define SKIP  25
#define NEGINF (-CUDART_INF_F)
#define FULL  0xFFFFFFFFu

// Strictly monotone float -> uint32 key (order-preserving bijection) + inverse
static __device__ __forceinline__ unsigned fkey(float f) {
    unsigned u = __float_as_uint(f);
    return u ^ ((unsigned)((int)u >> 31) | 0x80000000u);
}
static __device__ __forceinline__ float fkey_inv(unsigned k) {
    unsigned m = (k & 0x80000000u) ? 0x80000000u : 0xFFFFFFFFu;
    return __uint_as_float(k ^ m);
}

__global__ void __launch_bounds__(256, 4)
greedy_matching_kernel(const float* __restrict__ x, float* __restrict__ out) {
    const int warp = (blockIdx.x * blockDim.x + threadIdx.x) >> 5;
    const int lane = threadIdx.x & 31;

    const float* __restrict__ base = x + (size_t)warp * (VSZ * NU);
    float* __restrict__ pi_out = out + BATCH + (size_t)warp * VSZ;

    // Skip phase: sel = 0, weight 0, no mask change.
    for (int t = lane; t < SKIP; t += 32) pi_out[t] = 0.0f;

    // STRIDED ownership (coalesced 128B loads): lane l owns j = l, l+32,
    // l+64, l+96; j = 128 real only on lane 0 (b4 = -inf elsewhere).
    float b0 = 0.f, b1 = 0.f, b2 = 0.f, b3 = 0.f;
    float b4 = (lane == 0) ? 0.f : NEGINF;
    const float z0 = (lane == 0) ? 0.f : 1.f;   // skip (j=0) weight forced to 0
    const unsigned onebit = 1u << lane;
    float size = 0.f;

    // Ring of 3 prefetched rows; running row pointer p (refills rows 28..255).
    const float* p = base + SKIP * NU;
    float a0,a1,a2,a3,a4, c0,c1,c2,c3,c4, e0,e1,e2,e3,e4;
    a0 = p[lane]; a1 = p[lane+32]; a2 = p[lane+64]; a3 = p[lane+96]; a4 = p[128];
    p += NU;
    c0 = p[lane]; c1 = p[lane+32]; c2 = p[lane+64]; c3 = p[lane+96]; c4 = p[128];
    p += NU;
    e0 = p[lane]; e1 = p[lane+32]; e2 = p[lane+64]; e3 = p[lane+96]; e4 = p[128];
    p += NU;

    // One greedy step on ring buffer B*; REFILL = reload B* from row *p.
    // Fast path (unique max-key lane): that lane's in-lane argmax IS the
    // global argmax (strict '>' keeps the smallest owned j; unique lane =>
    // no cross-lane tie). Multi-lane key tie (popc>1, ~never on gaussian
    // data): exact min-j via REDUX.min fallback.
#define STAGE(B0,B1,B2,B3,B4, T, REFILL)                                       \
    do {                                                                       \
        float f0 = fmaf(B0, z0, b0);                                           \
        float f1 = B1 + b1;                                                    \
        float f2 = B2 + b2;                                                    \
        float f3 = B3 + b3;                                                    \
        float f4 = B4 + b4;                                                    \
        if (REFILL) {                                                          \
            B0 = p[lane]; B1 = p[lane+32]; B2 = p[lane+64]; B3 = p[lane+96];   \
            B4 = p[128]; p += NU;                                              \
        }                                                                      \
        float m01 = fmaxf(f0, f1), m23 = fmaxf(f2, f3);                        \
        float m03 = fmaxf(m01, m23);                                           \
        float lm  = fmaxf(m03, f4);                                            \
        int jA = (f1 > f0)  ? lane + 32 : lane;                                \
        int jB = (f3 > f2)  ? lane + 96 : lane + 64;                           \
        int jlo = (m23 > m01) ? jB : jA;                                       \
        int li  = (f4 > m03) ? 128 : jlo;                                      \
        unsigned mk = fkey(lm);                                                \
        unsigned gk = __reduce_max_sync(FULL, mk);                             \
        unsigned eq = __ballot_sync(FULL, mk == gk);                           \
        int s;                                                                 \
        if (__popc(eq) == 1) {                                                 \
            /* winner-local bias update: SHFL for s stays OFF the chain */     \
            if ((eq == onebit) && li != 0) {                                   \
                int tier = li >> 5;                                            \
                if (tier == 0) b0 = NEGINF;                                    \
                else if (tier == 1) b1 = NEGINF;                               \
                else if (tier == 2) b2 = NEGINF;                               \
                else if (tier == 3) b3 = NEGINF;                               \
                else b4 = NEGINF;       /* li == 128, lane 0 */                \
            }                                                                  \
            s = __shfl_sync(FULL, li, __ffs(eq) - 1);                          \
        } else {                                                               \
            unsigned cand = (mk == gk) ? (unsigned)li : FULL;                  \
            s = (int)__reduce_min_sync(FULL, cand);                            \
            int d = s - lane;                                                  \
            if (d == 0 && s != 0) b0 = NEGINF;                                 \
            if (d == 32)  b1 = NEGINF;                                         \
            if (d == 64)  b2 = NEGINF;                                         \
            if (d == 96)  b3 = NEGINF;                                         \
            if (d == 128) b4 = NEGINF;                                         \
        }                                                                      \
        size += fkey_inv(gk);                                                  \
        if (lane == 0) pi_out[T] = __int2float_rn(s);                          \
    } while (0)

    // Main loop: 76 groups (t = 25..250), refills rows 28..255 exactly.
#pragma unroll 1
    for (int t = SKIP; t < VSZ - 5; t += 3) {
        STAGE(a0, a1, a2, a3, a4, t,     1);
        STAGE(c0, c1, c2, c3, c4, t + 1, 1);
        STAGE(e0, e1, e2, e3, e4, t + 2, 1);
    }
    // Tail: rows 253, 254, 255 — no refill.
    STAGE(a0, a1, a2, a3, a4, VSZ - 3, 0);
    STAGE(c0, c1, c2, c3, c4, VSZ - 2, 0);
    STAGE(e0, e1, e2, e3, e4, VSZ - 1, 0);

    if (lane == 0) out[warp] = -size;
}

extern "C" void kernel_launch(void* const* d_in, const int* in_sizes, int n_in,
                              void* d_out, int out_size) {
    const float* x = (const float*)d_in[0];
    float* out = (float*)d_out;
    greedy_matching_kernel<<<BATCH / 8, 256>>>(x, out);
}

// round 11
// speedup vs baseline: 1.5692x; 1.1091x over previous
#include <cuda_runtime.h>
#include <cstdint>
#include <math_constants.h>

#define BATCH 4096
#define VSZ   256
#define NU    129
#define SKIP  25
#define NEGINF (-CUDART_INF_F)
#define FULL  0xFFFFFFFFu

#define ROW_BYTES   516
#define GROUP_ROWS  4
#define GROUP_BYTES 2064                     // 516*4, 16B multiple
#define FIRST_ROW   24                       // 516*24 is 16B aligned
#define NGROUPS     58
#define NSLOTS      3
#define WPB         4

// Strictly monotone float -> uint32 key (order-preserving bijection) + inverse
static __device__ __forceinline__ unsigned fkey(float f) {
    unsigned u = __float_as_uint(f);
    return u ^ ((unsigned)((int)u >> 31) | 0x80000000u);
}
static __device__ __forceinline__ float fkey_inv(unsigned k) {
    unsigned m = (k & 0x80000000u) ? 0x80000000u : 0xFFFFFFFFu;
    return __uint_as_float(k ^ m);
}

static __device__ __forceinline__ uint32_t smem_u32(const void* p) {
    uint32_t a;
    asm("{ .reg .u64 t; cvta.to.shared.u64 t, %1; cvt.u32.u64 %0, t; }" : "=r"(a) : "l"(p));
    return a;
}
static __device__ __forceinline__ void mbar_init(uint32_t mbar, uint32_t cnt) {
    asm volatile("mbarrier.init.shared.b64 [%0], %1;" :: "r"(mbar), "r"(cnt) : "memory");
}
static __device__ __forceinline__ void mbar_expect_tx(uint32_t mbar, uint32_t bytes) {
    asm volatile("mbarrier.arrive.expect_tx.shared.b64 _, [%0], %1;"
                 :: "r"(mbar), "r"(bytes) : "memory");
}
static __device__ __forceinline__ void bulk_g2s(uint32_t dst, const void* src, uint32_t bytes, uint32_t mbar) {
    asm volatile("cp.async.bulk.shared::cta.global.mbarrier::complete_tx::bytes [%0], [%1], %2, [%3];"
                 :: "r"(dst), "l"(src), "r"(bytes), "r"(mbar) : "memory");
}
static __device__ __forceinline__ void mbar_wait(uint32_t mbar, uint32_t parity) {
    uint32_t done;
    asm volatile("{\n\t.reg .pred p;\n\t"
                 "mbarrier.try_wait.parity.acquire.cta.shared::cta.b64 p, [%1], %2;\n\t"
                 "selp.b32 %0, 1, 0, p;\n\t}"
                 : "=r"(done) : "r"(mbar), "r"(parity) : "memory");
    if (!done) {
        asm volatile("{\n\t.reg .pred P1;\n\t"
                     "W_%=:\n\t"
                     "mbarrier.try_wait.parity.acquire.cta.shared::cta.b64 P1, [%0], %1, 0x989680;\n\t"
                     "@P1 bra.uni D_%=;\n\t"
                     "bra.uni W_%=;\n\t"
                     "D_%=:\n\t}"
                     :: "r"(mbar), "r"(parity) : "memory");
    }
}

__global__ void __launch_bounds__(128, 7)
greedy_matching_kernel(const float* __restrict__ x, float* __restrict__ out) {
    __shared__ __align__(128) unsigned char sbuf[WPB][NSLOTS][GROUP_BYTES];
    __shared__ __align__(8)   unsigned long long smbar[WPB][NSLOTS];

    const int wib  = threadIdx.x >> 5;
    const int lane = threadIdx.x & 31;
    const int warp = blockIdx.x * WPB + wib;

    const float* __restrict__ base = x + (size_t)warp * (VSZ * NU);
    float* __restrict__ pi_out = out + BATCH + (size_t)warp * VSZ;

    const uint32_t sb  = smem_u32(&sbuf[wib][0][0]);
    const uint32_t mbb = smem_u32(&smbar[wib][0]);

    // lane 0: init per-warp mbarriers, fence, prime the 3-slot ring (groups 0..2)
    if (lane == 0) {
        mbar_init(mbb + 0, 1); mbar_init(mbb + 8, 1); mbar_init(mbb + 16, 1);
        asm volatile("fence.proxy.async.shared::cta;" ::: "memory");
#pragma unroll
        for (int s = 0; s < NSLOTS; ++s) {
            mbar_expect_tx(mbb + 8u * s, GROUP_BYTES);
            bulk_g2s(sb + s * GROUP_BYTES,
                     base + (size_t)(FIRST_ROW + GROUP_ROWS * s) * NU,
                     GROUP_BYTES, mbb + 8u * s);
        }
    }
    __syncwarp();

    // Skip phase: sel = 0, weight 0, no mask change.
    for (int t = lane; t < SKIP; t += 32) pi_out[t] = 0.0f;

    // STRIDED ownership: lane l owns j = l, l+32, l+64, l+96; j = 128 real
    // only on lane 0 (b4 = -inf elsewhere). Bias: 0 = available, -inf = matched.
    float b0 = 0.f, b1 = 0.f, b2 = 0.f, b3 = 0.f;
    float b4 = (lane == 0) ? 0.f : NEGINF;
    const float z0 = (lane == 0) ? 0.f : 1.f;  // forces skip weight to 0 on lane 0
    const unsigned onebit = 1u << lane;
    float size = 0.f;

    // One greedy step on smem row `rp`, emitting pi[T].
    // Fast path (unique max-key lane): that lane's in-lane argmax IS the
    // global argmax (strict '>' keeps smallest owned j; unique lane => no
    // cross-lane tie). Multi-lane key tie (~never on gaussian data): exact
    // min-j via REDUX.min fallback.
#define STEP(rp, T)                                                            \
    do {                                                                       \
        float w0 = (rp)[lane];                                                 \
        float w1 = (rp)[lane + 32];                                            \
        float w2 = (rp)[lane + 64];                                            \
        float w3 = (rp)[lane + 96];                                            \
        float w4 = (rp)[128];                                                  \
        float f0 = fmaf(w0, z0, b0);                                           \
        float f1 = w1 + b1;                                                    \
        float f2 = w2 + b2;                                                    \
        float f3 = w3 + b3;                                                    \
        float f4 = w4 + b4;                                                    \
        float m01 = fmaxf(f0, f1), m23 = fmaxf(f2, f3);                        \
        float m03 = fmaxf(m01, m23);                                           \
        float lm  = fmaxf(m03, f4);                                            \
        int jA = (f1 > f0)  ? lane + 32 : lane;                                \
        int jB = (f3 > f2)  ? lane + 96 : lane + 64;                           \
        int jlo = (m23 > m01) ? jB : jA;                                       \
        int li  = (f4 > m03) ? 128 : jlo;                                      \
        unsigned mk = fkey(lm);                                                \
        unsigned gk = __reduce_max_sync(FULL, mk);                             \
        unsigned eq = __ballot_sync(FULL, mk == gk);                           \
        int s;                                                                 \
        if (__popc(eq) == 1) {                                                 \
            /* winner-local bias update: SHFL for s stays OFF the chain */     \
            if ((eq == onebit) && li != 0) {                                   \
                int tier = li >> 5;                                            \
                if (tier == 0) b0 = NEGINF;                                    \
                else if (tier == 1) b1 = NEGINF;                               \
                else if (tier == 2) b2 = NEGINF;                               \
                else if (tier == 3) b3 = NEGINF;                               \
                else b4 = NEGINF;       /* li == 128, lane 0 */                \
            }                                                                  \
            s = __shfl_sync(FULL, li, __ffs(eq) - 1);                          \
        } else {                                                               \
            unsigned cand = (mk == gk) ? (unsigned)li : FULL;                  \
            s = (int)__reduce_min_sync(FULL, cand);                            \
            int d = s - lane;                                                  \
            if (d == 0 && s != 0) b0 = NEGINF;                                 \
            if (d == 32)  b1 = NEGINF;                                         \
            if (d == 64)  b2 = NEGINF;                                         \
            if (d == 96)  b3 = NEGINF;                                         \
            if (d == 128) b4 = NEGINF;                                         \
        }                                                                      \
        size += fkey_inv(gk);                                                  \
        if (lane == 0) pi_out[T] = __int2float_rn(s);                          \
    } while (0)

    int stage = 0, phase = 0;

    // Group 0 (rows 24..27): row 24 is in the skip phase, consume rows 1..3.
    {
        mbar_wait(mbb + 0, 0);
        const unsigned char* sp = &sbuf[wib][0][0];
        STEP((const float*)(sp + 1 * ROW_BYTES), 25);
        STEP((const float*)(sp + 2 * ROW_BYTES), 26);
        STEP((const float*)(sp + 3 * ROW_BYTES), 27);
        if (lane == 0) {  // refill with group 3
            mbar_expect_tx(mbb + 0, GROUP_BYTES);
            bulk_g2s(sb + 0,
                     base + (size_t)(FIRST_ROW + GROUP_ROWS * NSLOTS) * NU,
                     GROUP_BYTES, mbb + 0);
        }
        stage = 1;
    }

    // Groups 1..57: 4 steps each; refill group g+3 while g+3 < 58.
    // Safe: the last STEP's REDUX/ballot converges the warp after every lane's
    // LDS of this slot has produced its value, so lane 0's refill cannot race.
#pragma unroll 1
    for (int g = 1; g < NGROUPS; ++g) {
        mbar_wait(mbb + 8u * stage, phase);
        const unsigned char* sp = &sbuf[wib][stage][0];
        const int t0 = FIRST_ROW + GROUP_ROWS * g;
        STEP((const float*)(sp + 0 * ROW_BYTES), t0 + 0);
        STEP((const float*)(sp + 1 * ROW_BYTES), t0 + 1);
        STEP((const float*)(sp + 2 * ROW_BYTES), t0 + 2);
        STEP((const float*)(sp + 3 * ROW_BYTES), t0 + 3);
        if (lane == 0 && g + NSLOTS < NGROUPS) {
            mbar_expect_tx(mbb + 8u * stage, GROUP_BYTES);
            bulk_g2s(sb + stage * GROUP_BYTES,
                     base + (size_t)(t0 + GROUP_ROWS * NSLOTS) * NU,
                     GROUP_BYTES, mbb + 8u * stage);
        }
        if (++stage == NSLOTS) { stage = 0; phase ^= 1; }
    }

    if (lane == 0) out[warp] = -size;
}

extern "C" void kernel_launch(void* const* d_in, const int* in_sizes, int n_in,
                              void* d_out, int out_size) {
    const float* x = (const float*)d_in[0];
    float* out = (float*)d_out;
    greedy_matching_kernel<<<BATCH / WPB, 128>>>(x, out);
}

// round 12
// speedup vs baseline: 1.6010x; 1.0203x over previous
#include <cuda_runtime.h>
#include <cstdint>
#include <math_constants.h>

#define BATCH 4096
#define VSZ   256
#define NU    129
#define SKIP  25
#define NEGINF (-CUDART_INF_F)
#define FULL  0xFFFFFFFFu

#define ROW_BYTES   516
#define GROUP_ROWS  4
#define GROUP_BYTES 2064                     // 516*4, 16B multiple
#define FIRST_ROW   24                       // 516*24 is 16B aligned
#define NGROUPS     58
#define NSLOTS      3
#define WPB         4

// Strictly monotone float -> uint32 key (order-preserving bijection) + inverse
static __device__ __forceinline__ unsigned fkey(float f) {
    unsigned u = __float_as_uint(f);
    return u ^ ((unsigned)((int)u >> 31) | 0x80000000u);
}
static __device__ __forceinline__ float fkey_inv(unsigned k) {
    unsigned m = (k & 0x80000000u) ? 0x80000000u : 0xFFFFFFFFu;
    return __uint_as_float(k ^ m);
}

static __device__ __forceinline__ uint32_t smem_u32(const void* p) {
    uint32_t a;
    asm("{ .reg .u64 t; cvta.to.shared.u64 t, %1; cvt.u32.u64 %0, t; }" : "=r"(a) : "l"(p));
    return a;
}
static __device__ __forceinline__ void mbar_init(uint32_t mbar, uint32_t cnt) {
    asm volatile("mbarrier.init.shared.b64 [%0], %1;" :: "r"(mbar), "r"(cnt) : "memory");
}
static __device__ __forceinline__ void mbar_expect_tx(uint32_t mbar, uint32_t bytes) {
    asm volatile("mbarrier.arrive.expect_tx.shared.b64 _, [%0], %1;"
                 :: "r"(mbar), "r"(bytes) : "memory");
}
static __device__ __forceinline__ void bulk_g2s(uint32_t dst, const void* src, uint32_t bytes, uint32_t mbar) {
    asm volatile("cp.async.bulk.shared::cta.global.mbarrier::complete_tx::bytes [%0], [%1], %2, [%3];"
                 :: "r"(dst), "l"(src), "r"(bytes), "r"(mbar) : "memory");
}
static __device__ __forceinline__ void mbar_wait(uint32_t mbar, uint32_t parity) {
    uint32_t done;
    asm volatile("{\n\t.reg .pred p;\n\t"
                 "mbarrier.try_wait.parity.acquire.cta.shared::cta.b64 p, [%1], %2;\n\t"
                 "selp.b32 %0, 1, 0, p;\n\t}"
                 : "=r"(done) : "r"(mbar), "r"(parity) : "memory");
    if (!done) {
        asm volatile("{\n\t.reg .pred P1;\n\t"
                     "W_%=:\n\t"
                     "mbarrier.try_wait.parity.acquire.cta.shared::cta.b64 P1, [%0], %1, 0x989680;\n\t"
                     "@P1 bra.uni D_%=;\n\t"
                     "bra.uni W_%=;\n\t"
                     "D_%=:\n\t}"
                     :: "r"(mbar), "r"(parity) : "memory");
    }
}

__global__ void __launch_bounds__(128, 7)
greedy_matching_kernel(const float* __restrict__ x, float* __restrict__ out) {
    __shared__ __align__(128) unsigned char sbuf[WPB][NSLOTS][GROUP_BYTES];
    __shared__ __align__(8)   unsigned long long smbar[WPB][NSLOTS];

    const int wib  = threadIdx.x >> 5;
    const int lane = threadIdx.x & 31;
    const int warp = blockIdx.x * WPB + wib;

    const float* __restrict__ base = x + (size_t)warp * (VSZ * NU);
    float* __restrict__ pi_out = out + BATCH + (size_t)warp * VSZ;

    const uint32_t sb  = smem_u32(&sbuf[wib][0][0]);
    const uint32_t mbb = smem_u32(&smbar[wib][0]);

    // lane 0: init per-warp mbarriers, fence, prime the 3-slot ring (groups 0..2)
    if (lane == 0) {
        mbar_init(mbb + 0, 1); mbar_init(mbb + 8, 1); mbar_init(mbb + 16, 1);
        asm volatile("fence.proxy.async.shared::cta;" ::: "memory");
#pragma unroll
        for (int s = 0; s < NSLOTS; ++s) {
            mbar_expect_tx(mbb + 8u * s, GROUP_BYTES);
            bulk_g2s(sb + s * GROUP_BYTES,
                     base + (size_t)(FIRST_ROW + GROUP_ROWS * s) * NU,
                     GROUP_BYTES, mbb + 8u * s);
        }
    }
    __syncwarp();

    // Skip phase: sel = 0, weight 0, no mask change.
    for (int t = lane; t < SKIP; t += 32) pi_out[t] = 0.0f;

    // STRIDED ownership: lane l owns j = l, l+32, l+64, l+96; j = 128 real
    // only on lane 0 (b4 = -inf elsewhere). Bias: 0 = available, -inf = matched.
    float b0 = 0.f, b1 = 0.f, b2 = 0.f, b3 = 0.f;
    float b4 = (lane == 0) ? 0.f : NEGINF;
    const float z0 = (lane == 0) ? 0.f : 1.f;  // forces skip weight to 0 on lane 0
    const unsigned onebit = 1u << lane;
    float size = 0.f;   // PER-LANE accumulator; butterfly-summed at the end

    // One greedy step on smem row `rp`, emitting pi[T].
    // Fast path (unique max-key lane): that lane's in-lane argmax IS the
    // global argmax (strict '>' keeps smallest owned j; unique lane => no
    // cross-lane tie). The winner lane does EVERYTHING locally: bias update,
    // size accumulation (its lm == the selected weight, bit-exact), and the
    // pi store — no shfl/ffs on the recurrence. Multi-lane key tie (~never
    // on gaussian data): exact min-j via REDUX.min fallback.
#define STEP(rp, T)                                                            \
    do {                                                                       \
        float w0 = (rp)[lane];                                                 \
        float w1 = (rp)[lane + 32];                                            \
        float w2 = (rp)[lane + 64];                                            \
        float w3 = (rp)[lane + 96];                                            \
        float w4 = (rp)[128];                                                  \
        float f0 = fmaf(w0, z0, b0);                                           \
        float f1 = w1 + b1;                                                    \
        float f2 = w2 + b2;                                                    \
        float f3 = w3 + b3;                                                    \
        float f4 = w4 + b4;                                                    \
        float m01 = fmaxf(f0, f1), m23 = fmaxf(f2, f3);                        \
        float m03 = fmaxf(m01, m23);                                           \
        float lm  = fmaxf(m03, f4);                                            \
        int jA = (f1 > f0)  ? lane + 32 : lane;                                \
        int jB = (f3 > f2)  ? lane + 96 : lane + 64;                           \
        int jlo = (m23 > m01) ? jB : jA;                                       \
        int li  = (f4 > m03) ? 128 : jlo;                                      \
        unsigned mk = fkey(lm);                                                \
        unsigned gk = __reduce_max_sync(FULL, mk);                             \
        unsigned eq = __ballot_sync(FULL, mk == gk);                           \
        if (__popc(eq) == 1) {                                                 \
            bool win = (eq == onebit);                                         \
            if (win) {                                                         \
                size += lm;                                                    \
                if (li != 0) {                                                 \
                    int tier = li >> 5;                                        \
                    if (tier == 0) b0 = NEGINF;                                \
                    else if (tier == 1) b1 = NEGINF;                           \
                    else if (tier == 2) b2 = NEGINF;                           \
                    else if (tier == 3) b3 = NEGINF;                           \
                    else b4 = NEGINF;       /* li == 128, lane 0 */            \
                }                                                              \
                pi_out[T] = __int2float_rn(li);                                \
            }                                                                  \
        } else {                                                               \
            unsigned cand = (mk == gk) ? (unsigned)li : FULL;                  \
            int s = (int)__reduce_min_sync(FULL, cand);                        \
            int d = s - lane;                                                  \
            if (d == 0 && s != 0) b0 = NEGINF;                                 \
            if (d == 32)  b1 = NEGINF;                                         \
            if (d == 64)  b2 = NEGINF;                                         \
            if (d == 96)  b3 = NEGINF;                                         \
            if (d == 128) b4 = NEGINF;                                         \
            /* owner lane of s books the weight (s==128 owned by lane 0) */    \
            int owner = (s == 128) ? 0 : (s & 31);                             \
            if (lane == owner) size += fkey_inv(gk);                           \
            if (lane == 0) pi_out[T] = __int2float_rn(s);                      \
        }                                                                      \
    } while (0)

    int stage = 0, phase = 0;

    // Group 0 (rows 24..27): row 24 is in the skip phase, consume rows 1..3.
    {
        mbar_wait(mbb + 0, 0);
        const unsigned char* sp = &sbuf[wib][0][0];
        STEP((const float*)(sp + 1 * ROW_BYTES), 25);
        STEP((const float*)(sp + 2 * ROW_BYTES), 26);
        STEP((const float*)(sp + 3 * ROW_BYTES), 27);
        if (lane == 0) {  // refill with group 3
            mbar_expect_tx(mbb + 0, GROUP_BYTES);
            bulk_g2s(sb + 0,
                     base + (size_t)(FIRST_ROW + GROUP_ROWS * NSLOTS) * NU,
                     GROUP_BYTES, mbb + 0);
        }
        stage = 1;
    }

    // Groups 1..57: 4 steps each; refill group g+3 while g+3 < 58.
    // Safe: the last STEP's REDUX/ballot converges the warp after every lane's
    // LDS of this slot has produced its value, so lane 0's refill cannot race.
#pragma unroll 1
    for (int g = 1; g < NGROUPS; ++g) {
        mbar_wait(mbb + 8u * stage, phase);
        const unsigned char* sp = &sbuf[wib][stage][0];
        const int t0 = FIRST_ROW + GROUP_ROWS * g;
        STEP((const float*)(sp + 0 * ROW_BYTES), t0 + 0);
        STEP((const float*)(sp + 1 * ROW_BYTES), t0 + 1);
        STEP((const float*)(sp + 2 * ROW_BYTES), t0 + 2);
        STEP((const float*)(sp + 3 * ROW_BYTES), t0 + 3);
        if (lane == 0 && g + NSLOTS < NGROUPS) {
            mbar_expect_tx(mbb + 8u * stage, GROUP_BYTES);
            bulk_g2s(sb + stage * GROUP_BYTES,
                     base + (size_t)(t0 + GROUP_ROWS * NSLOTS) * NU,
                     GROUP_BYTES, mbb + 8u * stage);
        }
        if (++stage == NSLOTS) { stage = 0; phase ^= 1; }
    }

    // Butterfly-sum the per-lane size accumulators (deterministic order).
#pragma unroll
    for (int o = 16; o; o >>= 1) size += __shfl_xor_sync(FULL, size, o);
    if (lane == 0) out[warp] = -size;
}

extern "C" void kernel_launch(void* const* d_in, const int* in_sizes, int n_in,
                              void* d_out, int out_size) {
    const float* x = (const float*)d_in[0];
    float* out = (float*)d_out;
    greedy_matching_kernel<<<BATCH / WPB, 128>>>(x, out);
}